// round 8
// baseline (speedup 1.0000x reference)
#include <cuda_runtime.h>
#include <cuda_bf16.h>

#define SEQ   128
#define BATCH 256
#define OBS   64
#define HID   1024
#define G4    4096          // 4*HID
#define K0L0  64            // x part of layer0 K
#define KTOT0 1088          // 64 + 1024
#define KTOT1 2048          // 1024 + 1024
#define NC0   (KTOT0/32)    // 34 chunks
#define NC1   (KTOT1/32)    // 64 chunks
#define BH    (BATCH*HID)

#define ASTR 40                        // smem row stride (floats): 8-bank shift/row
#define AS_BUF (128*ASTR)              // 5120 floats per A stage
#define BS_BUF (64*ASTR)               // 2560 floats per B stage
#define STAGES 3
#define SMEM_BYTES (STAGES*(AS_BUF+BS_BUF)*4)   // 92160 B

// permutation inside each 8-wide k-group: logical j -> physical ((j&3)<<1)|(j>>2)
__device__ __host__ __forceinline__ int pp8(int j) { return ((j & 3) << 1) | ((j >> 2) & 1); }
__device__ __host__ __forceinline__ int physpos(int k) { return (k & ~7) | pp8(k & 7); }

// ---------------- scratch (static device memory; no allocations) ----------------
__device__ __align__(16) float g_PW0[(size_t)G4 * KTOT0];   // tf32, gate-interleaved, k-permuted
__device__ __align__(16) float g_PW1[(size_t)G4 * KTOT1];
__device__ __align__(16) float g_PB0[G4];
__device__ __align__(16) float g_PB1[G4];
__device__ __align__(16) float g_W1p[512 * HID];            // tf32, k-permuted MLP weights
__device__ __align__(16) float g_W2p[128 * 512];
__device__ __align__(16) float g_W3p[64 * 128];
__device__ __align__(16) float g_xr[(size_t)SEQ * BATCH * OBS];  // x rounded+permuted
// exact logical buffers (outputs / LN)
__device__ __align__(16) float g_h0r[2][BH];
__device__ __align__(16) float g_c0r[2][BH];
__device__ __align__(16) float g_c1r[2][BH];
__device__ __align__(16) float g_hs[(size_t)SEQ * BH];
// GEMM-A feeds: rounded + permuted
__device__ __align__(16) float g_hg0[2][BH];                // layer0 h -> layer1 A
__device__ __align__(16) float g_h0m[2][BH];                // masked, for layer0 next step
__device__ __align__(16) float g_h1m[2][BH];                // masked, for layer1 next step
// masked c (exact, logical)
__device__ __align__(16) float g_c0m[2][BH];
__device__ __align__(16) float g_c1m[2][BH];
__device__ __align__(16) float g_ln[(size_t)SEQ * BH];      // rounded+permuted
__device__ __align__(16) float g_a1[(size_t)SEQ * BATCH * 512];  // rounded+permuted
__device__ __align__(16) float g_a2[(size_t)SEQ * BATCH * 128];  // rounded+permuted
__device__ __align__(16) float g_a3[(size_t)SEQ * BATCH * 64];   // exact logical

// ---------------- helpers ----------------
__device__ __forceinline__ unsigned tf32_bits(float x) {
    unsigned u; asm("cvt.rna.tf32.f32 %0, %1;" : "=r"(u) : "f"(x)); return u;
}
__device__ __forceinline__ float tf32f(float x) { return __uint_as_float(tf32_bits(x)); }

__device__ __forceinline__ void mma_tf32(float* c, const unsigned* a, const unsigned* b) {
    asm volatile(
        "mma.sync.aligned.m16n8k8.row.col.f32.tf32.tf32.f32 "
        "{%0,%1,%2,%3}, {%4,%5,%6,%7}, {%8,%9}, {%0,%1,%2,%3};"
        : "+f"(c[0]), "+f"(c[1]), "+f"(c[2]), "+f"(c[3])
        : "r"(a[0]), "r"(a[1]), "r"(a[2]), "r"(a[3]), "r"(b[0]), "r"(b[1]));
}

__device__ __forceinline__ void cpasync16(float* smem_ptr, const float* gptr) {
    unsigned s = (unsigned)__cvta_generic_to_shared(smem_ptr);
    asm volatile("cp.async.ca.shared.global [%0], [%1], 16;" :: "r"(s), "l"(gptr));
}
__device__ __forceinline__ void cp_commit() { asm volatile("cp.async.commit_group;"); }
template<int N> __device__ __forceinline__ void cp_wait() {
    asm volatile("cp.async.wait_group %0;" :: "n"(N));
}

__device__ __forceinline__ float sigm(float x) { return 1.f / (1.f + __expf(-x)); }
__device__ __forceinline__ float eluf(float x) { return x > 0.f ? x : (__expf(x) - 1.f); }

// ---------------- packing kernels ----------------
__global__ void pack_kernel(const float* __restrict__ Wih0, const float* __restrict__ Whh0,
                            const float* __restrict__ bih0, const float* __restrict__ bhh0,
                            const float* __restrict__ Wih1, const float* __restrict__ Whh1,
                            const float* __restrict__ bih1, const float* __restrict__ bhh1) {
    int j = blockIdx.x;              // packed row: j = unit*4 + gate
    int u = j >> 2, g = j & 3;
    int src = g * HID + u;
    if (blockIdx.y == 0) {
        for (int k = threadIdx.x; k < KTOT0; k += blockDim.x) {
            float v = (k < K0L0) ? Wih0[src * OBS + k] : Whh0[src * HID + (k - K0L0)];
            g_PW0[(size_t)j * KTOT0 + physpos(k)] = tf32f(v);
        }
        if (threadIdx.x == 0) g_PB0[j] = bih0[src] + bhh0[src];
    } else {
        for (int k = threadIdx.x; k < KTOT1; k += blockDim.x) {
            float v = (k < HID) ? Wih1[src * HID + k] : Whh1[src * HID + (k - HID)];
            g_PW1[(size_t)j * KTOT1 + physpos(k)] = tf32f(v);
        }
        if (threadIdx.x == 0) g_PB1[j] = bih1[src] + bhh1[src];
    }
}

__global__ void pack_w(const float* __restrict__ W1, const float* __restrict__ W2,
                       const float* __restrict__ W3) {
    int which = blockIdx.y;
    const float* src; float* dst; int n, k;
    if (which == 0)      { src = W1; dst = g_W1p; n = 512; k = HID; }
    else if (which == 1) { src = W2; dst = g_W2p; n = 128; k = 512; }
    else                 { src = W3; dst = g_W3p; n = 64;  k = 128; }
    for (int i = blockIdx.x * blockDim.x + threadIdx.x; i < n * k;
         i += gridDim.x * blockDim.x) {
        int r = i / k, c = i % k;
        dst[(size_t)r * k + physpos(c)] = tf32f(src[i]);
    }
}

__global__ void round_x(const float* __restrict__ x) {
    size_t i = (size_t)blockIdx.x * blockDim.x + threadIdx.x;
    size_t row = i / OBS; int c = (int)(i % OBS);
    g_xr[row * OBS + physpos(c)] = tf32f(x[i]);
}

// ---------------- initial masked state (step 0) ----------------
__global__ void init_masked(const float* __restrict__ h0, const float* __restrict__ c0,
                            const int* __restrict__ done) {
    size_t i = (size_t)blockIdx.x * blockDim.x + threadIdx.x;   // over BH
    size_t r = i / HID; int u = (int)(i % HID);
    float m = 1.f - (float)done[r];
    size_t op = r * HID + physpos(u);
    g_h0m[0][op] = tf32f(h0[i] * m);
    g_h1m[0][op] = tf32f(h0[BH + i] * m);
    g_c0m[0][i] = c0[i] * m;
    g_c1m[0][i] = c0[BH + i] * m;
}

// ---------------- fused LSTM: layer1(t) || layer0(t+1), cp.async 3-stage ----------------
__global__ __launch_bounds__(256, 2) void lstm_comb_kernel(
    const int* __restrict__ done, int t, int mode)
{
    extern __shared__ float sdyn[];
    float* As = sdyn;                         // STAGES x 128x32 (stride 40)
    float* Bs = sdyn + STAGES * AS_BUF;       // STAGES x 64x32

    int layer, step, bx2;
    if (mode == 0) { layer = 0; step = t; bx2 = blockIdx.x; }
    else if (blockIdx.x < 128) { layer = 1; step = t; bx2 = blockIdx.x; }
    else { layer = 0; step = t + 1; bx2 = blockIdx.x - 128; if (step >= SEQ) return; }

    const float *A0, *Aprev, *cprev, *PW, *PB;
    float *hraw, *hg, *hm, *craw, *cm;
    int K0len, NC, Ktot;
    bool l0 = (layer == 0);
    if (l0) {
        A0 = g_xr + (size_t)step * BATCH * OBS; K0len = K0L0; NC = NC0; Ktot = KTOT0;
        PW = g_PW0; PB = g_PB0;
        Aprev = g_h0m[step & 1];
        cprev = g_c0m[step & 1];
        hraw = g_h0r[step & 1]; hg = g_hg0[step & 1];
        hm = g_h0m[(step + 1) & 1];
        cm = g_c0m[(step + 1) & 1]; craw = g_c0r[step & 1];
    } else {
        A0 = g_hg0[step & 1]; K0len = HID; NC = NC1; Ktot = KTOT1;
        PW = g_PW1; PB = g_PB1;
        Aprev = g_h1m[step & 1];
        cprev = g_c1m[step & 1];
        hraw = g_hs + (size_t)step * BH; hg = nullptr;
        hm = g_h1m[(step + 1) & 1];
        cm = g_c1m[(step + 1) & 1]; craw = g_c1r[step & 1];
    }

    int tid = threadIdx.x, lane = tid & 31, warp = tid >> 5;
    int m0 = (bx2 & 1) * 128;
    int nrow0 = (bx2 >> 1) * 64;
    int wm = warp >> 1, wn = warp & 1;        // 4x2 warp grid, 32x32 per warp
    int ar = lane >> 2, ac = lane & 3;

    float acc[2][4][4];
#pragma unroll
    for (int i = 0; i < 2; i++)
#pragma unroll
        for (int j = 0; j < 4; j++)
#pragma unroll
            for (int k = 0; k < 4; k++) acc[i][j][k] = 0.f;

    auto issue = [&](int ck, int st) {
        int kk = ck * 32;
        bool inx = kk < K0len;
        const float* base = inx ? A0 + (size_t)m0 * K0len + kk
                                : Aprev + (size_t)m0 * HID + (kk - K0len);
        int rs = inx ? K0len : HID;
        float* Ad = As + st * AS_BUF;
#pragma unroll
        for (int i = 0; i < 4; i++) {
            int q = tid + i * 256; int r = q >> 3; int c4 = (q & 7) * 4;
            cpasync16(&Ad[r * ASTR + c4], base + (size_t)r * rs + c4);
        }
        const float* bb = PW + (size_t)nrow0 * Ktot + kk;
        float* Bd = Bs + st * BS_BUF;
#pragma unroll
        for (int i = 0; i < 2; i++) {
            int q = tid + i * 256; int r = q >> 3; int c4 = (q & 7) * 4;
            cpasync16(&Bd[r * ASTR + c4], bb + (size_t)r * Ktot + c4);
        }
        cp_commit();
    };

    issue(0, 0);
    issue(1, 1);

    for (int it = 0; it < NC; it++) {
        if (it < NC - 1) cp_wait<1>(); else cp_wait<0>();
        __syncthreads();
        int nxt = it + 2;
        if (nxt < NC) issue(nxt, nxt % STAGES);

        const float* Ab = As + (it % STAGES) * AS_BUF;
        const float* Bb = Bs + (it % STAGES) * BS_BUF;
#pragma unroll
        for (int ksi = 0; ksi < 4; ksi++) {
            int ks = ksi * 8;
            unsigned a[2][4], b[4][2];
#pragma unroll
            for (int mf = 0; mf < 2; mf++) {
                int rb = wm * 32 + mf * 16 + ar;
                float2 t0 = *(const float2*)&Ab[rb * ASTR + ks + 2 * ac];
                float2 t1 = *(const float2*)&Ab[(rb + 8) * ASTR + ks + 2 * ac];
                a[mf][0] = __float_as_uint(t0.x); a[mf][2] = __float_as_uint(t0.y);
                a[mf][1] = __float_as_uint(t1.x); a[mf][3] = __float_as_uint(t1.y);
            }
#pragma unroll
            for (int nf = 0; nf < 4; nf++) {
                int nb = wn * 32 + nf * 8 + ar;
                float2 tb = *(const float2*)&Bb[nb * ASTR + ks + 2 * ac];
                b[nf][0] = __float_as_uint(tb.x); b[nf][1] = __float_as_uint(tb.y);
            }
#pragma unroll
            for (int mf = 0; mf < 2; mf++)
#pragma unroll
                for (int nf = 0; nf < 4; nf++)
                    mma_tf32(acc[mf][nf], a[mf], b[nf]);
        }
        __syncthreads();
    }

    // ---- epilogue: bias + gate merge + LSTM cell + stores ----
    const int* dnext = done + (step + 1) * BATCH;
    bool has_next = (step + 1 < SEQ);
#pragma unroll
    for (int mf = 0; mf < 2; mf++) {
#pragma unroll
        for (int nf = 0; nf < 4; nf++) {
            int npl = wn * 32 + nf * 8 + ac * 2;
            int nglob = nrow0 + npl;               // packed col = unit*4 + gate
            float bb0 = g_PB0[0];                  // placeholder to keep regs tight (overwritten)
            bb0 = PB[nglob];
            float bb1 = PB[nglob + 1];
            float v0 = acc[mf][nf][0] + bb0;
            float v1 = acc[mf][nf][1] + bb1;
            float v2 = acc[mf][nf][2] + bb0;
            float v3 = acc[mf][nf][3] + bb1;
            float p0 = __shfl_xor_sync(0xffffffffu, v0, 1);
            float p1 = __shfl_xor_sync(0xffffffffu, v1, 1);
            float p2 = __shfl_xor_sync(0xffffffffu, v2, 1);
            float p3 = __shfl_xor_sync(0xffffffffu, v3, 1);
            if ((lane & 1) == 0) {                 // even lanes: (i,f); partner: (g,o)
                int u = nglob >> 2;
                int up = physpos(u);
                int r0 = m0 + wm * 32 + mf * 16 + ar;
                {
                    float mn = has_next ? 1.f - (float)dnext[r0] : 0.f;
                    float cp = cprev[(size_t)r0 * HID + u];        // pre-masked
                    float cn = sigm(v1) * cp + sigm(v0) * tanhf(p0);
                    float hn = sigm(p1) * tanhf(cn);
                    size_t o = (size_t)r0 * HID + u;
                    size_t op = (size_t)r0 * HID + up;
                    hraw[o] = hn;
                    if (l0) hg[op] = tf32f(hn);
                    hm[op] = tf32f(hn * mn);
                    cm[o] = cn * mn; craw[o] = cn;
                }
                {
                    int r1 = r0 + 8;
                    float mn = has_next ? 1.f - (float)dnext[r1] : 0.f;
                    float cp = cprev[(size_t)r1 * HID + u];
                    float cn = sigm(v3) * cp + sigm(v2) * tanhf(p2);
                    float hn = sigm(p3) * tanhf(cn);
                    size_t o = (size_t)r1 * HID + u;
                    size_t op = (size_t)r1 * HID + up;
                    hraw[o] = hn;
                    if (l0) hg[op] = tf32f(hn);
                    hm[op] = tf32f(hn * mn);
                    cm[o] = cn * mn; craw[o] = cn;
                }
            }
        }
    }
}

// ---------------- LayerNorm (exact input, rounded+permuted output) ----------------
__global__ __launch_bounds__(256) void ln_kernel(const float* __restrict__ gam,
                                                 const float* __restrict__ bet) {
    int row = blockIdx.x;
    int tid = threadIdx.x, lane = tid & 31, w = tid >> 5;
    const float4 v = ((const float4*)(g_hs + (size_t)row * HID))[tid];
    float s = v.x + v.y + v.z + v.w;
    float q = v.x * v.x + v.y * v.y + v.z * v.z + v.w * v.w;
    __shared__ float sh[18];
#pragma unroll
    for (int o = 16; o; o >>= 1) {
        s += __shfl_xor_sync(0xffffffffu, s, o);
        q += __shfl_xor_sync(0xffffffffu, q, o);
    }
    if (!lane) { sh[w] = s; sh[w + 8] = q; }
    __syncthreads();
    if (tid == 0) {
        float S = 0.f, Q = 0.f;
        for (int i = 0; i < 8; i++) { S += sh[i]; Q += sh[i + 8]; }
        float mu = S * (1.f / HID);
        float var = Q * (1.f / HID) - mu * mu;
        sh[16] = mu; sh[17] = rsqrtf(var + 1e-5f);
    }
    __syncthreads();
    float mu = sh[16], rs = sh[17];
    float4 g4 = ((const float4*)gam)[tid];
    float4 b4 = ((const float4*)bet)[tid];
    float* dst = g_ln + (size_t)row * HID;
    int c0 = tid * 4;
    dst[physpos(c0 + 0)] = tf32f((v.x - mu) * rs * g4.x + b4.x);
    dst[physpos(c0 + 1)] = tf32f((v.y - mu) * rs * g4.y + b4.y);
    dst[physpos(c0 + 2)] = tf32f((v.z - mu) * rs * g4.z + b4.z);
    dst[physpos(c0 + 3)] = tf32f((v.w - mu) * rs * g4.w + b4.w);
}

// ---------------- MLP GEMM + ELU, cp.async 3-stage ----------------
__global__ __launch_bounds__(256, 2) void mlp_gemm(const float* __restrict__ bias, int which) {
    extern __shared__ float sdyn[];
    float* As = sdyn;
    float* Bs = sdyn + STAGES * AS_BUF;
    const float* A; const float* W; float* C; int N, K;
    if (which == 0)      { A = g_ln; W = g_W1p; C = g_a1; N = 512; K = 1024; }
    else if (which == 1) { A = g_a1; W = g_W2p; C = g_a2; N = 128; K = 512; }
    else                 { A = g_a2; W = g_W3p; C = g_a3; N = 64;  K = 128; }

    int tid = threadIdx.x, lane = tid & 31, warp = tid >> 5;
    int m0 = blockIdx.x * 128;
    int n0 = blockIdx.y * 64;
    int wm = warp >> 1, wn = warp & 1;
    int ar = lane >> 2, ac = lane & 3;

    float acc[2][4][4];
#pragma unroll
    for (int i = 0; i < 2; i++)
#pragma unroll
        for (int j = 0; j < 4; j++)
#pragma unroll
            for (int k = 0; k < 4; k++) acc[i][j][k] = 0.f;

    const int NC = K / 32;

    auto issue = [&](int ck, int st) {
        int kk = ck * 32;
        const float* ab = A + (size_t)m0 * K + kk;
        float* Ad = As + st * AS_BUF;
#pragma unroll
        for (int i = 0; i < 4; i++) {
            int q = tid + i * 256; int r = q >> 3; int c4 = (q & 7) * 4;
            cpasync16(&Ad[r * ASTR + c4], ab + (size_t)r * K + c4);
        }
        const float* bb = W + (size_t)n0 * K + kk;
        float* Bd = Bs + st * BS_BUF;
#pragma unroll
        for (int i = 0; i < 2; i++) {
            int q = tid + i * 256; int r = q >> 3; int c4 = (q & 7) * 4;
            cpasync16(&Bd[r * ASTR + c4], bb + (size_t)r * K + c4);
        }
        cp_commit();
    };

    issue(0, 0);
    issue(1, 1);

    for (int it = 0; it < NC; it++) {
        if (it < NC - 1) cp_wait<1>(); else cp_wait<0>();
        __syncthreads();
        int nxt = it + 2;
        if (nxt < NC) issue(nxt, nxt % STAGES);

        const float* Ab = As + (it % STAGES) * AS_BUF;
        const float* Bb = Bs + (it % STAGES) * BS_BUF;
#pragma unroll
        for (int ksi = 0; ksi < 4; ksi++) {
            int ks = ksi * 8;
            unsigned a[2][4], b[4][2];
#pragma unroll
            for (int mf = 0; mf < 2; mf++) {
                int rb = wm * 32 + mf * 16 + ar;
                float2 t0 = *(const float2*)&Ab[rb * ASTR + ks + 2 * ac];
                float2 t1 = *(const float2*)&Ab[(rb + 8) * ASTR + ks + 2 * ac];
                a[mf][0] = __float_as_uint(t0.x); a[mf][2] = __float_as_uint(t0.y);
                a[mf][1] = __float_as_uint(t1.x); a[mf][3] = __float_as_uint(t1.y);
            }
#pragma unroll
            for (int nf = 0; nf < 4; nf++) {
                int nb = wn * 32 + nf * 8 + ar;
                float2 tb = *(const float2*)&Bb[nb * ASTR + ks + 2 * ac];
                b[nf][0] = __float_as_uint(tb.x); b[nf][1] = __float_as_uint(tb.y);
            }
#pragma unroll
            for (int mf = 0; mf < 2; mf++)
#pragma unroll
                for (int nf = 0; nf < 4; nf++)
                    mma_tf32(acc[mf][nf], a[mf], b[nf]);
        }
        __syncthreads();
    }

#pragma unroll
    for (int mf = 0; mf < 2; mf++) {
#pragma unroll
        for (int nf = 0; nf < 4; nf++) {
            int col = n0 + wn * 32 + nf * 8 + ac * 2;
            int r0 = m0 + wm * 32 + mf * 16 + ar;
            float b0 = bias[col], b1 = bias[col + 1];
            float e0 = eluf(acc[mf][nf][0] + b0);
            float e1 = eluf(acc[mf][nf][1] + b1);
            float e2 = eluf(acc[mf][nf][2] + b0);
            float e3 = eluf(acc[mf][nf][3] + b1);
            if (which < 2) {   // feeds another GEMM: round + permute on store
                int p0c = physpos(col), p1c = physpos(col + 1);
                C[(size_t)r0 * N + p0c]       = tf32f(e0);
                C[(size_t)r0 * N + p1c]       = tf32f(e1);
                C[(size_t)(r0 + 8) * N + p0c] = tf32f(e2);
                C[(size_t)(r0 + 8) * N + p1c] = tf32f(e3);
            } else {           // feeds value head: exact, logical
                C[(size_t)r0 * N + col]           = e0;
                C[(size_t)r0 * N + col + 1]       = e1;
                C[(size_t)(r0 + 8) * N + col]     = e2;
                C[(size_t)(r0 + 8) * N + col + 1] = e3;
            }
        }
    }
}

// ---------------- final value head ----------------
__global__ __launch_bounds__(256) void value_kernel(const float* __restrict__ Wv,
                                                    const float* __restrict__ bv,
                                                    float* __restrict__ out) {
    int warp = threadIdx.x >> 5, lane = threadIdx.x & 31;
    int row = blockIdx.x * 8 + warp;
    const float* a = g_a3 + (size_t)row * 64;
    float s = a[lane] * Wv[lane] + a[lane + 32] * Wv[lane + 32];
#pragma unroll
    for (int o = 16; o; o >>= 1) s += __shfl_xor_sync(0xffffffffu, s, o);
    if (lane == 0) out[row] = s + bv[0];
}

// ---------------- copy final states into output ----------------
__global__ void copy_states(float* __restrict__ out) {
    const int last = (SEQ - 1) & 1;                 // = 1
    for (size_t i = blockIdx.x * blockDim.x + threadIdx.x; i < 4 * (size_t)BH;
         i += (size_t)gridDim.x * blockDim.x) {
        float v;
        if (i < BH)                  v = g_h0r[last][i];
        else if (i < 2 * (size_t)BH) v = g_hs[(size_t)(SEQ - 1) * BH + (i - BH)];
        else if (i < 3 * (size_t)BH) v = g_c0r[last][i - 2 * BH];
        else                         v = g_c1r[last][i - 3 * BH];
        out[SEQ * BATCH + i] = v;
    }
}

// ---------------- launch ----------------
extern "C" void kernel_launch(void* const* d_in, const int* in_sizes, int n_in,
                              void* d_out, int out_size) {
    const float* x     = (const float*)d_in[0];
    const int*   done  = (const int*)  d_in[1];
    const float* h0    = (const float*)d_in[2];
    const float* c0    = (const float*)d_in[3];
    const float* Wih0  = (const float*)d_in[4];
    const float* Whh0  = (const float*)d_in[5];
    const float* bih0  = (const float*)d_in[6];
    const float* bhh0  = (const float*)d_in[7];
    const float* Wih1  = (const float*)d_in[8];
    const float* Whh1  = (const float*)d_in[9];
    const float* bih1  = (const float*)d_in[10];
    const float* bhh1  = (const float*)d_in[11];
    const float* ln_g  = (const float*)d_in[12];
    const float* ln_b  = (const float*)d_in[13];
    const float* W1    = (const float*)d_in[14];
    const float* b1    = (const float*)d_in[15];
    const float* W2    = (const float*)d_in[16];
    const float* b2    = (const float*)d_in[17];
    const float* W3    = (const float*)d_in[18];
    const float* b3    = (const float*)d_in[19];
    const float* Wv    = (const float*)d_in[20];
    const float* bv    = (const float*)d_in[21];
    float* out = (float*)d_out;

    cudaFuncSetAttribute(lstm_comb_kernel, cudaFuncAttributeMaxDynamicSharedMemorySize, SMEM_BYTES);
    cudaFuncSetAttribute(mlp_gemm,         cudaFuncAttributeMaxDynamicSharedMemorySize, SMEM_BYTES);

    pack_kernel<<<dim3(G4, 2), 256>>>(Wih0, Whh0, bih0, bhh0, Wih1, Whh1, bih1, bhh1);
    pack_w<<<dim3(2048, 3), 256>>>(W1, W2, W3);
    round_x<<<(SEQ * BATCH * OBS) / 256, 256>>>(x);
    init_masked<<<BH / 256, 256>>>(h0, c0, done);

    // prologue: layer0 step 0
    lstm_comb_kernel<<<128, 256, SMEM_BYTES>>>(done, 0, 0);
    // combined: layer1(t) || layer0(t+1)
    for (int t = 0; t < SEQ; t++)
        lstm_comb_kernel<<<256, 256, SMEM_BYTES>>>(done, t, 1);

    ln_kernel<<<SEQ * BATCH, 256>>>(ln_g, ln_b);
    mlp_gemm<<<dim3(256, 8), 256, SMEM_BYTES>>>(b1, 0);
    mlp_gemm<<<dim3(256, 2), 256, SMEM_BYTES>>>(b2, 1);
    mlp_gemm<<<dim3(256, 1), 256, SMEM_BYTES>>>(b3, 2);
    value_kernel<<<SEQ * BATCH / 8, 256>>>(Wv, bv, out);
    copy_states<<<2048, 256>>>(out);
}

// round 11
// speedup vs baseline: 1.0419x; 1.0419x over previous
#include <cuda_runtime.h>
#include <cuda_bf16.h>

#define SEQ   128
#define BATCH 256
#define OBS   64
#define HID   1024
#define G4    4096          // 4*HID
#define K0L0  64            // x part of layer0 K
#define KTOT0 1088          // 64 + 1024
#define KTOT1 2048          // 1024 + 1024
#define NC0   (KTOT0/32)    // 34 chunks
#define NC1   (KTOT1/32)    // 64 chunks
#define BH    (BATCH*HID)

#define AS_STRIDE 36
#define AS_BUF    (128*AS_STRIDE)     // 4608 floats per stage
#define BS_BUF    (64*AS_STRIDE)      // 2304 floats per stage
#define STAGES 3
#define SMEM_FLOATS (STAGES*(AS_BUF+BS_BUF))
#define SMEM_BYTES  (SMEM_FLOATS*4)   // 82944 B

// ---------------- scratch (static device memory; no allocations) ----------------
__device__ __align__(16) float g_PW0[(size_t)G4 * KTOT0];   // tf32-rounded, gate-interleaved
__device__ __align__(16) float g_PW1[(size_t)G4 * KTOT1];
__device__ __align__(16) float g_PB0[G4];
__device__ __align__(16) float g_PB1[G4];
__device__ __align__(16) float g_W1p[512 * HID];            // tf32-rounded MLP weights
__device__ __align__(16) float g_W2p[128 * 512];
__device__ __align__(16) float g_W3p[64 * 128];
__device__ __align__(16) float g_xr[(size_t)SEQ * BATCH * OBS];  // x tf32-rounded
// exact logical buffers (outputs / LN input)
__device__ __align__(16) float g_h0r[2][BH];
__device__ __align__(16) float g_c0r[2][BH];
__device__ __align__(16) float g_c1r[2][BH];
__device__ __align__(16) float g_hs[(size_t)SEQ * BH];
// GEMM-A feeds: tf32-rounded, logical layout
__device__ __align__(16) float g_hg0[2][BH];                // layer0 h -> layer1 A
__device__ __align__(16) float g_h0m[2][BH];                // masked+rounded, layer0 next step
__device__ __align__(16) float g_h1m[2][BH];                // masked+rounded, layer1 next step
// masked c (exact)
__device__ __align__(16) float g_c0m[2][BH];
__device__ __align__(16) float g_c1m[2][BH];
__device__ __align__(16) float g_ln[(size_t)SEQ * BH];      // tf32-rounded
__device__ __align__(16) float g_a1[(size_t)SEQ * BATCH * 512];  // tf32-rounded
__device__ __align__(16) float g_a2[(size_t)SEQ * BATCH * 128];  // tf32-rounded
__device__ __align__(16) float g_a3[(size_t)SEQ * BATCH * 64];   // exact

// ---------------- helpers ----------------
__device__ __forceinline__ unsigned tf32_bits(float x) {
    unsigned u; asm("cvt.rna.tf32.f32 %0, %1;" : "=r"(u) : "f"(x)); return u;
}
__device__ __forceinline__ float tf32f(float x) { return __uint_as_float(tf32_bits(x)); }

__device__ __forceinline__ void mma_tf32(float* c, const unsigned* a, const unsigned* b) {
    asm volatile(
        "mma.sync.aligned.m16n8k8.row.col.f32.tf32.tf32.f32 "
        "{%0,%1,%2,%3}, {%4,%5,%6,%7}, {%8,%9}, {%0,%1,%2,%3};"
        : "+f"(c[0]), "+f"(c[1]), "+f"(c[2]), "+f"(c[3])
        : "r"(a[0]), "r"(a[1]), "r"(a[2]), "r"(a[3]), "r"(b[0]), "r"(b[1]));
}

__device__ __forceinline__ void cpasync16(float* smem_ptr, const float* gptr) {
    unsigned s = (unsigned)__cvta_generic_to_shared(smem_ptr);
    asm volatile("cp.async.ca.shared.global [%0], [%1], 16;" :: "r"(s), "l"(gptr));
}
__device__ __forceinline__ void cp_commit() { asm volatile("cp.async.commit_group;"); }
template<int N> __device__ __forceinline__ void cp_wait() {
    asm volatile("cp.async.wait_group %0;" :: "n"(N));
}

__device__ __forceinline__ float sigm(float x) { return 1.f / (1.f + __expf(-x)); }
__device__ __forceinline__ float eluf(float x) { return x > 0.f ? x : (__expf(x) - 1.f); }

// ---------------- weight packing (tf32-rounded, gate-interleaved rows) ----------------
__global__ void pack_kernel(const float* __restrict__ Wih0, const float* __restrict__ Whh0,
                            const float* __restrict__ bih0, const float* __restrict__ bhh0,
                            const float* __restrict__ Wih1, const float* __restrict__ Whh1,
                            const float* __restrict__ bih1, const float* __restrict__ bhh1) {
    int j = blockIdx.x;              // packed row: j = unit*4 + gate
    int u = j >> 2, g = j & 3;
    int src = g * HID + u;
    if (blockIdx.y == 0) {
        for (int k = threadIdx.x; k < KTOT0; k += blockDim.x) {
            float v = (k < K0L0) ? Wih0[src * OBS + k] : Whh0[src * HID + (k - K0L0)];
            g_PW0[(size_t)j * KTOT0 + k] = tf32f(v);
        }
        if (threadIdx.x == 0) g_PB0[j] = bih0[src] + bhh0[src];
    } else {
        for (int k = threadIdx.x; k < KTOT1; k += blockDim.x) {
            float v = (k < HID) ? Wih1[src * HID + k] : Whh1[src * HID + (k - HID)];
            g_PW1[(size_t)j * KTOT1 + k] = tf32f(v);
        }
        if (threadIdx.x == 0) g_PB1[j] = bih1[src] + bhh1[src];
    }
}

__global__ void pack_w(const float* __restrict__ W1, const float* __restrict__ W2,
                       const float* __restrict__ W3) {
    int which = blockIdx.y;
    const float* src; float* dst; int n;
    if (which == 0)      { src = W1; dst = g_W1p; n = 512 * HID; }
    else if (which == 1) { src = W2; dst = g_W2p; n = 128 * 512; }
    else                 { src = W3; dst = g_W3p; n = 64 * 128; }
    for (int i = blockIdx.x * blockDim.x + threadIdx.x; i < n; i += gridDim.x * blockDim.x)
        dst[i] = tf32f(src[i]);
}

__global__ void round_x(const float* __restrict__ x) {
    size_t i = (size_t)blockIdx.x * blockDim.x + threadIdx.x;
    g_xr[i] = tf32f(x[i]);
}

// ---------------- initial masked state (step 0) ----------------
__global__ void init_masked(const float* __restrict__ h0, const float* __restrict__ c0,
                            const int* __restrict__ done) {
    size_t i = (size_t)blockIdx.x * blockDim.x + threadIdx.x;   // over BH
    int b = (int)(i / HID);
    float m = 1.f - (float)done[b];
    g_h0m[0][i] = tf32f(h0[i] * m);
    g_h1m[0][i] = tf32f(h0[BH + i] * m);
    g_c0m[0][i] = c0[i] * m;
    g_c1m[0][i] = c0[BH + i] * m;
}

// ---------------- fused LSTM: layer1(t) || layer0(t+1), cp.async 3-stage ----------------
__global__ __launch_bounds__(256, 2) void lstm_comb_kernel(
    const int* __restrict__ done, int t, int mode)
{
    extern __shared__ float sdyn[];
    float* As = sdyn;                         // STAGES x 128x32 (stride 36)
    float* Bs = sdyn + STAGES * AS_BUF;       // STAGES x 64x32

    int layer, step, bx2;
    if (mode == 0) { layer = 0; step = t; bx2 = blockIdx.x; }
    else if (blockIdx.x < 128) { layer = 1; step = t; bx2 = blockIdx.x; }
    else { layer = 0; step = t + 1; bx2 = blockIdx.x - 128; if (step >= SEQ) return; }

    const float *A0, *Aprev, *cprev, *PW, *PB;
    float *hraw, *hg, *hm, *craw, *cm;
    int K0len, NC, Ktot;
    bool l0 = (layer == 0);
    if (l0) {
        A0 = g_xr + (size_t)step * BATCH * OBS; K0len = K0L0; NC = NC0; Ktot = KTOT0;
        PW = g_PW0; PB = g_PB0;
        Aprev = g_h0m[step & 1];
        cprev = g_c0m[step & 1];
        hraw = g_h0r[step & 1]; hg = g_hg0[step & 1];
        hm = g_h0m[(step + 1) & 1];
        cm = g_c0m[(step + 1) & 1]; craw = g_c0r[step & 1];
    } else {
        A0 = g_hg0[step & 1]; K0len = HID; NC = NC1; Ktot = KTOT1;
        PW = g_PW1; PB = g_PB1;
        Aprev = g_h1m[step & 1];
        cprev = g_c1m[step & 1];
        hraw = g_hs + (size_t)step * BH; hg = nullptr;
        hm = g_h1m[(step + 1) & 1];
        cm = g_c1m[(step + 1) & 1]; craw = g_c1r[step & 1];
    }

    int tid = threadIdx.x, lane = tid & 31, warp = tid >> 5;
    int m0 = (bx2 & 1) * 128;
    int nrow0 = (bx2 >> 1) * 64;
    int wm = warp >> 1, wn = warp & 1;        // 4x2 warp grid, 32x32 per warp
    int ar = lane >> 2, ac = lane & 3;

    float acc[2][4][4];
#pragma unroll
    for (int i = 0; i < 2; i++)
#pragma unroll
        for (int j = 0; j < 4; j++)
#pragma unroll
            for (int k = 0; k < 4; k++) acc[i][j][k] = 0.f;

    auto issue = [&](int ck, int st) {
        int kk = ck * 32;
        bool inx = kk < K0len;                // uniform per chunk
        const float* base = inx ? A0 + (size_t)m0 * K0len + kk
                                : Aprev + (size_t)m0 * HID + (kk - K0len);
        int rs = inx ? K0len : HID;
        float* Ad = As + st * AS_BUF;
#pragma unroll
        for (int i = 0; i < 4; i++) {
            int q = tid + i * 256; int r = q >> 3; int c4 = (q & 7) * 4;
            cpasync16(&Ad[r * AS_STRIDE + c4], base + (size_t)r * rs + c4);
        }
        const float* bb = PW + (size_t)nrow0 * Ktot + kk;
        float* Bd = Bs + st * BS_BUF;
#pragma unroll
        for (int i = 0; i < 2; i++) {
            int q = tid + i * 256; int r = q >> 3; int c4 = (q & 7) * 4;
            cpasync16(&Bd[r * AS_STRIDE + c4], bb + (size_t)r * Ktot + c4);
        }
        cp_commit();
    };

    issue(0, 0);
    issue(1, 1);

    for (int it = 0; it < NC; it++) {
        if (it < NC - 1) cp_wait<1>(); else cp_wait<0>();
        __syncthreads();
        int nxt = it + 2;
        if (nxt < NC) issue(nxt, nxt % STAGES);

        const float* Ab = As + (it % STAGES) * AS_BUF;
        const float* Bb = Bs + (it % STAGES) * BS_BUF;
#pragma unroll
        for (int ksi = 0; ksi < 4; ksi++) {
            int ks = ksi * 8;
            unsigned a[2][4], b[4][2];
#pragma unroll
            for (int mf = 0; mf < 2; mf++) {
                int rb = wm * 32 + mf * 16 + ar;
                a[mf][0] = __float_as_uint(Ab[rb * AS_STRIDE + ks + ac]);
                a[mf][1] = __float_as_uint(Ab[(rb + 8) * AS_STRIDE + ks + ac]);
                a[mf][2] = __float_as_uint(Ab[rb * AS_STRIDE + ks + ac + 4]);
                a[mf][3] = __float_as_uint(Ab[(rb + 8) * AS_STRIDE + ks + ac + 4]);
            }
#pragma unroll
            for (int nf = 0; nf < 4; nf++) {
                int nb = wn * 32 + nf * 8 + ar;
                b[nf][0] = __float_as_uint(Bb[nb * AS_STRIDE + ks + ac]);
                b[nf][1] = __float_as_uint(Bb[nb * AS_STRIDE + ks + ac + 4]);
            }
#pragma unroll
            for (int mf = 0; mf < 2; mf++)
#pragma unroll
                for (int nf = 0; nf < 4; nf++)
                    mma_tf32(acc[mf][nf], a[mf], b[nf]);
        }
        __syncthreads();
    }

    // ---- epilogue: bias + gate merge (shfl lane^1) + LSTM cell + stores ----
    const int* dnext = done + (step + 1) * BATCH;
    bool has_next = (step + 1 < SEQ);
#pragma unroll
    for (int mf = 0; mf < 2; mf++) {
#pragma unroll
        for (int nf = 0; nf < 4; nf++) {
            int npl = wn * 32 + nf * 8 + ac * 2;
            int nglob = nrow0 + npl;               // packed col = unit*4 + gate
            float bb0 = PB[nglob], bb1 = PB[nglob + 1];
            float v0 = acc[mf][nf][0] + bb0;
            float v1 = acc[mf][nf][1] + bb1;
            float v2 = acc[mf][nf][2] + bb0;
            float v3 = acc[mf][nf][3] + bb1;
            float p0 = __shfl_xor_sync(0xffffffffu, v0, 1);
            float p1 = __shfl_xor_sync(0xffffffffu, v1, 1);
            float p2 = __shfl_xor_sync(0xffffffffu, v2, 1);
            float p3 = __shfl_xor_sync(0xffffffffu, v3, 1);
            if ((lane & 1) == 0) {                 // even lanes: (i,f); partner: (g,o)
                int u = nglob >> 2;
                int r0 = m0 + wm * 32 + mf * 16 + ar;
                {
                    float mn = has_next ? 1.f - (float)dnext[r0] : 0.f;
                    float cp = cprev[(size_t)r0 * HID + u];        // pre-masked
                    float cn = sigm(v1) * cp + sigm(v0) * tanhf(p0);
                    float hn = sigm(p1) * tanhf(cn);
                    size_t o = (size_t)r0 * HID + u;
                    hraw[o] = hn;
                    if (l0) hg[o] = tf32f(hn);
                    hm[o] = tf32f(hn * mn);
                    cm[o] = cn * mn; craw[o] = cn;
                }
                {
                    int r1 = r0 + 8;
                    float mn = has_next ? 1.f - (float)dnext[r1] : 0.f;
                    float cp = cprev[(size_t)r1 * HID + u];
                    float cn = sigm(v3) * cp + sigm(v2) * tanhf(p2);
                    float hn = sigm(p3) * tanhf(cn);
                    size_t o = (size_t)r1 * HID + u;
                    hraw[o] = hn;
                    if (l0) hg[o] = tf32f(hn);
                    hm[o] = tf32f(hn * mn);
                    cm[o] = cn * mn; craw[o] = cn;
                }
            }
        }
    }
}

// ---------------- LayerNorm (exact input, tf32-rounded output) ----------------
__global__ __launch_bounds__(256) void ln_kernel(const float* __restrict__ gam,
                                                 const float* __restrict__ bet) {
    int row = blockIdx.x;
    int tid = threadIdx.x, lane = tid & 31, w = tid >> 5;
    const float4 v = ((const float4*)(g_hs + (size_t)row * HID))[tid];
    float s = v.x + v.y + v.z + v.w;
    float q = v.x * v.x + v.y * v.y + v.z * v.z + v.w * v.w;
    __shared__ float sh[18];
#pragma unroll
    for (int o = 16; o; o >>= 1) {
        s += __shfl_xor_sync(0xffffffffu, s, o);
        q += __shfl_xor_sync(0xffffffffu, q, o);
    }
    if (!lane) { sh[w] = s; sh[w + 8] = q; }
    __syncthreads();
    if (tid == 0) {
        float S = 0.f, Q = 0.f;
        for (int i = 0; i < 8; i++) { S += sh[i]; Q += sh[i + 8]; }
        float mu = S * (1.f / HID);
        float var = Q * (1.f / HID) - mu * mu;
        sh[16] = mu; sh[17] = rsqrtf(var + 1e-5f);
    }
    __syncthreads();
    float mu = sh[16], rs = sh[17];
    float4 g4 = ((const float4*)gam)[tid];
    float4 b4 = ((const float4*)bet)[tid];
    float4 o;
    o.x = tf32f((v.x - mu) * rs * g4.x + b4.x);
    o.y = tf32f((v.y - mu) * rs * g4.y + b4.y);
    o.z = tf32f((v.z - mu) * rs * g4.z + b4.z);
    o.w = tf32f((v.w - mu) * rs * g4.w + b4.w);
    ((float4*)(g_ln + (size_t)row * HID))[tid] = o;
}

// ---------------- MLP GEMM + ELU, cp.async 3-stage ----------------
__global__ __launch_bounds__(256, 2) void mlp_gemm(const float* __restrict__ bias, int which) {
    extern __shared__ float sdyn[];
    float* As = sdyn;
    float* Bs = sdyn + STAGES * AS_BUF;
    const float* A; const float* W; float* C; int N, K;
    if (which == 0)      { A = g_ln; W = g_W1p; C = g_a1; N = 512; K = 1024; }
    else if (which == 1) { A = g_a1; W = g_W2p; C = g_a2; N = 128; K = 512; }
    else                 { A = g_a2; W = g_W3p; C = g_a3; N = 64;  K = 128; }

    int tid = threadIdx.x, lane = tid & 31, warp = tid >> 5;
    int m0 = blockIdx.x * 128;
    int n0 = blockIdx.y * 64;
    int wm = warp >> 1, wn = warp & 1;
    int ar = lane >> 2, ac = lane & 3;

    float acc[2][4][4];
#pragma unroll
    for (int i = 0; i < 2; i++)
#pragma unroll
        for (int j = 0; j < 4; j++)
#pragma unroll
            for (int k = 0; k < 4; k++) acc[i][j][k] = 0.f;

    const int NC = K / 32;

    auto issue = [&](int ck, int st) {
        int kk = ck * 32;
        const float* ab = A + (size_t)m0 * K + kk;
        float* Ad = As + st * AS_BUF;
#pragma unroll
        for (int i = 0; i < 4; i++) {
            int q = tid + i * 256; int r = q >> 3; int c4 = (q & 7) * 4;
            cpasync16(&Ad[r * AS_STRIDE + c4], ab + (size_t)r * K + c4);
        }
        const float* bb = W + (size_t)n0 * K + kk;
        float* Bd = Bs + st * BS_BUF;
#pragma unroll
        for (int i = 0; i < 2; i++) {
            int q = tid + i * 256; int r = q >> 3; int c4 = (q & 7) * 4;
            cpasync16(&Bd[r * AS_STRIDE + c4], bb + (size_t)r * K + c4);
        }
        cp_commit();
    };

    issue(0, 0);
    issue(1, 1);

    for (int it = 0; it < NC; it++) {
        if (it < NC - 1) cp_wait<1>(); else cp_wait<0>();
        __syncthreads();
        int nxt = it + 2;
        if (nxt < NC) issue(nxt, nxt % STAGES);

        const float* Ab = As + (it % STAGES) * AS_BUF;
        const float* Bb = Bs + (it % STAGES) * BS_BUF;
#pragma unroll
        for (int ksi = 0; ksi < 4; ksi++) {
            int ks = ksi * 8;
            unsigned a[2][4], b[4][2];
#pragma unroll
            for (int mf = 0; mf < 2; mf++) {
                int rb = wm * 32 + mf * 16 + ar;
                a[mf][0] = __float_as_uint(Ab[rb * AS_STRIDE + ks + ac]);
                a[mf][1] = __float_as_uint(Ab[(rb + 8) * AS_STRIDE + ks + ac]);
                a[mf][2] = __float_as_uint(Ab[rb * AS_STRIDE + ks + ac + 4]);
                a[mf][3] = __float_as_uint(Ab[(rb + 8) * AS_STRIDE + ks + ac + 4]);
            }
#pragma unroll
            for (int nf = 0; nf < 4; nf++) {
                int nb = wn * 32 + nf * 8 + ar;
                b[nf][0] = __float_as_uint(Bb[nb * AS_STRIDE + ks + ac]);
                b[nf][1] = __float_as_uint(Bb[nb * AS_STRIDE + ks + ac + 4]);
            }
#pragma unroll
            for (int mf = 0; mf < 2; mf++)
#pragma unroll
                for (int nf = 0; nf < 4; nf++)
                    mma_tf32(acc[mf][nf], a[mf], b[nf]);
        }
        __syncthreads();
    }

#pragma unroll
    for (int mf = 0; mf < 2; mf++) {
#pragma unroll
        for (int nf = 0; nf < 4; nf++) {
            int col = n0 + wn * 32 + nf * 8 + ac * 2;
            int r0 = m0 + wm * 32 + mf * 16 + ar;
            float b0 = bias[col], b1 = bias[col + 1];
            float e0 = eluf(acc[mf][nf][0] + b0);
            float e1 = eluf(acc[mf][nf][1] + b1);
            float e2 = eluf(acc[mf][nf][2] + b0);
            float e3 = eluf(acc[mf][nf][3] + b1);
            if (which < 2) {                       // feeds another GEMM: round at store
                C[(size_t)r0 * N + col]           = tf32f(e0);
                C[(size_t)r0 * N + col + 1]       = tf32f(e1);
                C[(size_t)(r0 + 8) * N + col]     = tf32f(e2);
                C[(size_t)(r0 + 8) * N + col + 1] = tf32f(e3);
            } else {                               // feeds fp32 value head: exact
                C[(size_t)r0 * N + col]           = e0;
                C[(size_t)r0 * N + col + 1]       = e1;
                C[(size_t)(r0 + 8) * N + col]     = e2;
                C[(size_t)(r0 + 8) * N + col + 1] = e3;
            }
        }
    }
}

// ---------------- final value head ----------------
__global__ __launch_bounds__(256) void value_kernel(const float* __restrict__ Wv,
                                                    const float* __restrict__ bv,
                                                    float* __restrict__ out) {
    int warp = threadIdx.x >> 5, lane = threadIdx.x & 31;
    int row = blockIdx.x * 8 + warp;
    const float* a = g_a3 + (size_t)row * 64;
    float s = a[lane] * Wv[lane] + a[lane + 32] * Wv[lane + 32];
#pragma unroll
    for (int o = 16; o; o >>= 1) s += __shfl_xor_sync(0xffffffffu, s, o);
    if (lane == 0) out[row] = s + bv[0];
}

// ---------------- copy final states into output ----------------
__global__ void copy_states(float* __restrict__ out) {
    const int last = (SEQ - 1) & 1;                 // = 1
    for (size_t i = blockIdx.x * blockDim.x + threadIdx.x; i < 4 * (size_t)BH;
         i += (size_t)gridDim.x * blockDim.x) {
        float v;
        if (i < BH)                  v = g_h0r[last][i];
        else if (i < 2 * (size_t)BH) v = g_hs[(size_t)(SEQ - 1) * BH + (i - BH)];
        else if (i < 3 * (size_t)BH) v = g_c0r[last][i - 2 * BH];
        else                         v = g_c1r[last][i - 3 * BH];
        out[SEQ * BATCH + i] = v;
    }
}

// ---------------- launch ----------------
extern "C" void kernel_launch(void* const* d_in, const int* in_sizes, int n_in,
                              void* d_out, int out_size) {
    const float* x     = (const float*)d_in[0];
    const int*   done  = (const int*)  d_in[1];
    const float* h0    = (const float*)d_in[2];
    const float* c0    = (const float*)d_in[3];
    const float* Wih0  = (const float*)d_in[4];
    const float* Whh0  = (const float*)d_in[5];
    const float* bih0  = (const float*)d_in[6];
    const float* bhh0  = (const float*)d_in[7];
    const float* Wih1  = (const float*)d_in[8];
    const float* Whh1  = (const float*)d_in[9];
    const float* bih1  = (const float*)d_in[10];
    const float* bhh1  = (const float*)d_in[11];
    const float* ln_g  = (const float*)d_in[12];
    const float* ln_b  = (const float*)d_in[13];
    const float* W1    = (const float*)d_in[14];
    const float* b1    = (const float*)d_in[15];
    const float* W2    = (const float*)d_in[16];
    const float* b2    = (const float*)d_in[17];
    const float* W3    = (const float*)d_in[18];
    const float* b3    = (const float*)d_in[19];
    const float* Wv    = (const float*)d_in[20];
    const float* bv    = (const float*)d_in[21];
    float* out = (float*)d_out;

    cudaFuncSetAttribute(lstm_comb_kernel, cudaFuncAttributeMaxDynamicSharedMemorySize, SMEM_BYTES);
    cudaFuncSetAttribute(mlp_gemm,         cudaFuncAttributeMaxDynamicSharedMemorySize, SMEM_BYTES);

    pack_kernel<<<dim3(G4, 2), 256>>>(Wih0, Whh0, bih0, bhh0, Wih1, Whh1, bih1, bhh1);
    pack_w<<<dim3(2048, 3), 256>>>(W1, W2, W3);
    round_x<<<(SEQ * BATCH * OBS) / 256, 256>>>(x);
    init_masked<<<BH / 256, 256>>>(h0, c0, done);

    // prologue: layer0 step 0
    lstm_comb_kernel<<<128, 256, SMEM_BYTES>>>(done, 0, 0);
    // combined: layer1(t) || layer0(t+1)
    for (int t = 0; t < SEQ; t++)
        lstm_comb_kernel<<<256, 256, SMEM_BYTES>>>(done, t, 1);

    ln_kernel<<<SEQ * BATCH, 256>>>(ln_g, ln_b);
    mlp_gemm<<<dim3(256, 8), 256, SMEM_BYTES>>>(b1, 0);
    mlp_gemm<<<dim3(256, 2), 256, SMEM_BYTES>>>(b2, 1);
    mlp_gemm<<<dim3(256, 1), 256, SMEM_BYTES>>>(b3, 2);
    value_kernel<<<SEQ * BATCH / 8, 256>>>(Wv, bv, out);
    copy_states<<<2048, 256>>>(out);
}